// round 3
// baseline (speedup 1.0000x reference)
#include <cuda_runtime.h>

#define HT 160
#define WDx 160
#define HWPIX 25600
#define NB 2
#define NPIX (NB * HWPIX)
#define CCH 64
#define NSETC 32

typedef unsigned long long ull;

__device__ __forceinline__ ull pack2(float a, float b) {
    ull r; asm("mov.b64 %0, {%1, %2};" : "=l"(r) : "f"(a), "f"(b)); return r;
}
__device__ __forceinline__ ull dup2(float a) {
    ull r; asm("mov.b64 %0, {%1, %1};" : "=l"(r) : "f"(a)); return r;
}
__device__ __forceinline__ ull fma2(ull a, ull b, ull c) {
    ull r; asm("fma.rn.f32x2 %0, %1, %2, %3;" : "=l"(r) : "l"(a), "l"(b), "l"(c)); return r;
}
__device__ __forceinline__ ull add2(ull a, ull b) {
    ull r; asm("add.rn.f32x2 %0, %1, %2;" : "=l"(r) : "l"(a), "l"(b)); return r;
}
__device__ __forceinline__ ull mul2(ull a, ull b) {
    ull r; asm("mul.rn.f32x2 %0, %1, %2;" : "=l"(r) : "l"(a), "l"(b)); return r;
}

// ---------------- scratch (device globals) ---------------------------------
__device__ float g_x[NPIX * CCH];      // LN1 output
__device__ float g_att[NPIX * NSETC];  // attention maps
__device__ float g_u1[NPIX * CCH];     // conv1x1a output
__device__ float g_uf[NPIX * CCH];     // 5x5 grouped conv output
__device__ float g_z[NPIX * CCH];      // pre-conv3 combined
__device__ float g_xmean[NB * CCH];
__device__ float g_sca[NB * CCH];
__device__ ull   g_kbwT2[16 * 37 * 128]; // duplicated-pair transposed kb weights

// ---------------- K0: prep kb weights: [g][k][m=o*32+n] duplicated ---------
__global__ void kbw_prep_kernel(const float* __restrict__ kb_w,
                                const float* __restrict__ kb_b) {
    int idx = blockIdx.x * 256 + threadIdx.x;
    if (idx >= 16 * 37 * 128) return;
    int m = idx & 127;
    int k = (idx >> 7) % 37;
    int g = idx / (37 * 128);
    int o = m >> 5, n = m & 31;
    float v = (k < 36) ? kb_w[n * 2304 + g * 144 + o * 36 + k]
                       : kb_b[n * 64 + g * 4 + o];
    g_kbwT2[idx] = dup2(v);
}

// ---------------- K1: fused LN1 + conv1x1a. 32-pixel tile, 256 thr ---------
__global__ void ln1_c11a_kernel(const float* __restrict__ inp,
                                const float* __restrict__ lnw,
                                const float* __restrict__ lnb,
                                const float* __restrict__ cw,
                                const float* __restrict__ cb) {
    __shared__ float xs[64][33];
    __shared__ float wT[64 * 64];  // [ic][oc]
    __shared__ float red1[8][33], red2[8][33];
    int tid = threadIdx.x;
    int w = tid >> 5, lane = tid & 31;
    int tile = blockIdx.x;
    int bi = tile / (HWPIX / 32);
    int hw0 = (tile % (HWPIX / 32)) * 32;
    // stage transposed conv weights
    for (int i = tid; i < 4096; i += 256) {
        int ic = i >> 6, oc = i & 63;
        wT[i] = cw[oc * 64 + ic];
    }
    // load this warp's 8 channels
    float xv[8];
    const float* src = inp + ((size_t)bi * 64 + w * 8) * HWPIX + hw0 + lane;
    float s = 0.f;
#pragma unroll
    for (int j = 0; j < 8; j++) { xv[j] = src[j * HWPIX]; s += xv[j]; }
    red1[w][lane] = s;
    __syncthreads();
    float mu = 0.f;
#pragma unroll
    for (int i = 0; i < 8; i++) mu += red1[i][lane];
    mu *= (1.f / 64.f);
    float q = 0.f;
#pragma unroll
    for (int j = 0; j < 8; j++) { float d = xv[j] - mu; q += d * d; }
    red2[w][lane] = q;
    __syncthreads();
    float var = 0.f;
#pragma unroll
    for (int i = 0; i < 8; i++) var += red2[i][lane];
    float rinv = rsqrtf(var * (1.f / 64.f) + 1e-6f);
    float* gxdst = g_x + ((size_t)bi * 64 + w * 8) * HWPIX + hw0 + lane;
#pragma unroll
    for (int j = 0; j < 8; j++) {
        int c = w * 8 + j;
        float xn = (xv[j] - mu) * rinv * lnw[c] + lnb[c];
        gxdst[j * HWPIX] = xn;
        xs[c][lane] = xn;
    }
    __syncthreads();
    // conv1x1: warp w computes oc = 8w..8w+8
    float acc[8];
#pragma unroll
    for (int j = 0; j < 8; j++) acc[j] = cb[w * 8 + j];
    for (int ic = 0; ic < 64; ic++) {
        float xvv = xs[ic][lane];
        float4 wa = *(const float4*)&wT[ic * 64 + w * 8];
        float4 wb = *(const float4*)&wT[ic * 64 + w * 8 + 4];
        acc[0] += wa.x * xvv; acc[1] += wa.y * xvv;
        acc[2] += wa.z * xvv; acc[3] += wa.w * xvv;
        acc[4] += wb.x * xvv; acc[5] += wb.y * xvv;
        acc[6] += wb.z * xvv; acc[7] += wb.w * xvv;
    }
    float* dst = g_u1 + ((size_t)bi * 64 + w * 8) * HWPIX + hw0 + lane;
#pragma unroll
    for (int j = 0; j < 8; j++) dst[j * HWPIX] = acc[j];
}

// ---------------- K2: per-(b,c) spatial mean of g_x ------------------------
__global__ void mean_kernel() {
    int bc = blockIdx.x;
    const float* src = g_x + (size_t)bc * HWPIX;
    float s = 0.f;
    for (int i = threadIdx.x; i < HWPIX; i += blockDim.x) s += src[i];
#pragma unroll
    for (int o = 16; o > 0; o >>= 1) s += __shfl_down_sync(0xffffffffu, s, o);
    __shared__ float red[16];
    if ((threadIdx.x & 31) == 0) red[threadIdx.x >> 5] = s;
    __syncthreads();
    if (threadIdx.x == 0) {
        float t = 0.f;
        for (int i = 0; i < (int)(blockDim.x >> 5); i++) t += red[i];
        g_xmean[bc] = t * (1.f / HWPIX);
    }
}

// ---------------- K3: sca = 1x1 conv on pooled means -----------------------
__global__ void sca_kernel(const float* __restrict__ w, const float* __restrict__ b) {
    int t = threadIdx.x;
    if (t < NB * CCH) {
        int bi = t >> 6, c = t & 63;
        float a = b[c];
#pragma unroll
        for (int k = 0; k < 64; k++) a += w[c * 64 + k] * g_xmean[bi * 64 + k];
        g_sca[t] = a;
    }
}

// ---------------- K4: attention path, 32-pixel tile ------------------------
__global__ void att_kernel(const float* __restrict__ c2a_w, const float* __restrict__ c2a_b,
                           const float* __restrict__ c2b_w, const float* __restrict__ c2b_b,
                           const float* __restrict__ attgamma) {
    __shared__ float as[8][880];      // per-warp halo: 8ch x 3rows x 36cols (+pad)
    __shared__ float wa[576], ba[32], bb[32], ag[32];
    __shared__ float wbT[16 * 32];    // [j][n]
    __shared__ float gs[16][33];
    int tid = threadIdx.x;
    int w = tid >> 5, lane = tid & 31;
    for (int i = tid; i < 576; i += 256) wa[i] = c2a_w[i];
    if (tid < 32) { ba[tid] = c2a_b[tid]; bb[tid] = c2b_b[tid]; ag[tid] = attgamma[tid]; }
    for (int i = tid; i < 512; i += 256) {
        int j = i >> 5, n = i & 31;
        wbT[i] = c2b_w[n * 16 + j];
    }
    int tile = blockIdx.x;
    int bi = tile / (HWPIX / 32);
    int hw0 = (tile % (HWPIX / 32)) * 32;
    int h = hw0 / WDx, w0 = hw0 - h * WDx;
    // stage 8 channels x 3 rows x 36 cols per warp (ch i<4 -> 4w+i, else 4w+28+i)
    const float* xb = g_x + (size_t)bi * 64 * HWPIX;
    for (int idx = lane; idx < 864; idx += 32) {
        int ch = idx / 108;
        int r = idx - ch * 108;
        int dy = r / 36, col = r - dy * 36;
        int gc = (ch < 4) ? (4 * w + ch) : (4 * w + 28 + ch);
        int hh = h + dy - 1, ww = w0 + col - 1;
        float v = ((unsigned)hh < HT && (unsigned)ww < WDx) ? xb[gc * HWPIX + hh * WDx + ww] : 0.f;
        as[w][ch * 108 + dy * 36 + col] = v;
    }
    __syncthreads();  // also covers weight staging
    // warp w computes gate outputs jj = 2w, 2w+1
#pragma unroll
    for (int jl = 0; jl < 2; jl++) {
        int jj = 2 * w + jl;
        float t0 = ba[jj], t1 = ba[jj + 16];
#pragma unroll
        for (int l = 0; l < 2; l++) {
            int ch0 = 2 * jl + l;       // channel 2*jj+l  -> local idx
            int ch1 = 4 + 2 * jl + l;   // channel 2*jj+32+l -> local idx
#pragma unroll
            for (int dy = 0; dy < 3; dy++) {
#pragma unroll
                for (int dx = 0; dx < 3; dx++) {
                    float x0 = as[w][ch0 * 108 + dy * 36 + lane + dx];
                    float x1 = as[w][ch1 * 108 + dy * 36 + lane + dx];
                    t0 += wa[jj * 18 + l * 9 + dy * 3 + dx] * x0;
                    t1 += wa[(jj + 16) * 18 + l * 9 + dy * 3 + dx] * x1;
                }
            }
        }
        gs[jj][lane] = t0 * t1;
    }
    __syncthreads();
    // warp w computes att for n = 4w..4w+4
    float aacc[4] = {0.f, 0.f, 0.f, 0.f};
    for (int j = 0; j < 16; j++) {
        float gv = gs[j][lane];
        float4 wv = *(const float4*)&wbT[j * 32 + 4 * w];
        aacc[0] += wv.x * gv; aacc[1] += wv.y * gv;
        aacc[2] += wv.z * gv; aacc[3] += wv.w * gv;
    }
    float* dst = g_att + ((size_t)bi * 32 + 4 * w) * HWPIX + hw0 + lane;
#pragma unroll
    for (int nl = 0; nl < 4; nl++)
        dst[nl * HWPIX] = (aacc[nl] + bb[4 * w + nl]) * ag[4 * w + nl];
}

// ---------------- K5: grouped 5x5 conv, 32-pixel tile ----------------------
#define UF_SMEM ((8 * 1456 + 6400 + 64) * 4)
__global__ void uf_kernel(const float* __restrict__ w5, const float* __restrict__ b5) {
    extern __shared__ float ufs[];
    float* us = ufs;                 // 8 warps x (8ch x 5rows x 36cols = 1440, pad 1456)
    float* ws = ufs + 8 * 1456;      // [g][ic][kk][oc] 6400
    float* bs = ws + 6400;           // 64
    int tid = threadIdx.x;
    int w = tid >> 5, lane = tid & 31;
    for (int i = tid; i < 6400; i += 256) {
        int oc = i & 3;
        int r = i >> 2;
        int g = r / 100;
        int r2 = r - g * 100;
        int ic = r2 / 25, kk = r2 - ic * 25;
        ws[i] = w5[((g * 4 + oc) * 4 + ic) * 25 + kk];
    }
    if (tid < 64) bs[tid] = b5[tid];
    int tile = blockIdx.x;
    int bi = tile / (HWPIX / 32);
    int hw0 = (tile % (HWPIX / 32)) * 32;
    int h = hw0 / WDx, w0 = hw0 - h * WDx;
    const float* ub = g_u1 + (size_t)bi * 64 * HWPIX;
    float* uw = us + w * 1456;
    for (int idx = lane; idx < 1440; idx += 32) {
        int ch = idx / 180;
        int r = idx - ch * 180;
        int dy = r / 36, col = r - dy * 36;
        int gc = 8 * w + ch;
        int hh = h + dy - 2, ww = w0 + col - 2;
        float v = ((unsigned)hh < HT && (unsigned)ww < WDx) ? ub[gc * HWPIX + hh * WDx + ww] : 0.f;
        uw[ch * 180 + dy * 36 + col] = v;
    }
    __syncthreads();
    float* dst = g_uf + ((size_t)bi * 64 + 8 * w) * HWPIX + hw0 + lane;
#pragma unroll
    for (int gl = 0; gl < 2; gl++) {
        int g = 2 * w + gl;
        float a0 = bs[g * 4], a1 = bs[g * 4 + 1], a2 = bs[g * 4 + 2], a3 = bs[g * 4 + 3];
#pragma unroll
        for (int ic = 0; ic < 4; ic++) {
            const float* ur = uw + (gl * 4 + ic) * 180;
#pragma unroll
            for (int dy = 0; dy < 5; dy++) {
#pragma unroll
                for (int dx = 0; dx < 5; dx++) {
                    float v = ur[dy * 36 + lane + dx];
                    const float4 wv = *(const float4*)&ws[(g * 100 + ic * 25 + dy * 5 + dx) * 4];
                    a0 += wv.x * v; a1 += wv.y * v; a2 += wv.z * v; a3 += wv.w * v;
                }
            }
        }
        dst[(gl * 4 + 0) * HWPIX] = a0;
        dst[(gl * 4 + 1) * HWPIX] = a1;
        dst[(gl * 4 + 2) * HWPIX] = a2;
        dst[(gl * 4 + 3) * HWPIX] = a3;
    }
}

// ---------------- K6: fused KBA, 128-pixel tile, 4 groups per block --------
#define KBA_SMEM_BYTES (37 * 128 * 8 + 37 * 64 * 8 + 32 * 65 * 8)
__global__ void kba_kernel(const float* __restrict__ ga1) {
    extern __shared__ char smem[];
    ull* Ws2     = (ull*)smem;                                // [37][128] dup pairs
    ull* patch2s = (ull*)(smem + 37 * 128 * 8);               // [37][64]
    ull* att2s   = (ull*)(smem + 37 * 128 * 8 + 37 * 64 * 8); // [32][65]

    int tid = threadIdx.x;
    int bi  = blockIdx.x / (HWPIX / 128);
    int hw0 = (blockIdx.x % (HWPIX / 128)) * 128;
    int g0  = blockIdx.y * 4;

    for (int idx = tid; idx < 32 * 64; idx += 256) {
        int n = idx >> 6, pp = idx & 63;
        const float2 v = *(const float2*)&g_att[((size_t)bi * 32 + n) * HWPIX + hw0 + 2 * pp];
        att2s[n * 65 + pp] = pack2(v.x, v.y);
    }

    int m_blk = tid & 15;
    int pp0   = (tid >> 4) * 4;
    int m0    = m_blk * 8;
    int o_out = m_blk >> 2;
    int n0    = (m_blk & 3) * 8;

    for (int gi = 0; gi < 4; gi++) {
        int g = g0 + gi;
        __syncthreads();
        // stage duplicated weights (coalesced)
        const ull* wsrc = g_kbwT2 + (size_t)g * 37 * 128;
        for (int idx = tid; idx < 37 * 128; idx += 256) Ws2[idx] = wsrc[idx];
        // stage patches
        for (int idx = tid; idx < 36 * 64; idx += 256) {
            int k = idx >> 6, pp = idx & 63;
            int ci = k / 9, kk = k - ci * 9;
            int dy = kk / 3, dx = kk - dy * 3;
            const float* ufc = g_uf + ((size_t)bi * 64 + g * 4 + ci) * HWPIX;
            float v0, v1;
            {
                int p = hw0 + 2 * pp;
                int h = p / WDx, w = p - h * WDx;
                int hy = h + dy - 1, wx = w + dx - 1;
                v0 = ((unsigned)hy < HT && (unsigned)wx < WDx) ? ufc[hy * WDx + wx] : 0.f;
            }
            {
                int p = hw0 + 2 * pp + 1;
                int h = p / WDx, w = p - h * WDx;
                int hy = h + dy - 1, wx = w + dx - 1;
                v1 = ((unsigned)hy < HT && (unsigned)wx < WDx) ? ufc[hy * WDx + wx] : 0.f;
            }
            patch2s[idx] = pack2(v0, v1);
        }
        if (tid < 64) patch2s[36 * 64 + tid] = pack2(1.f, 1.f);
        __syncthreads();

        ull acc[8][4];
#pragma unroll
        for (int j = 0; j < 8; j++)
#pragma unroll
            for (int q = 0; q < 4; q++) acc[j][q] = 0ull;

        for (int k = 0; k < 37; k++) {
            const ull* pvp = &patch2s[k * 64 + pp0];
            ull pv0 = pvp[0], pv1 = pvp[1], pv2 = pvp[2], pv3 = pvp[3];
            const ull* wp = &Ws2[k * 128 + m0];
#pragma unroll
            for (int j = 0; j < 8; j++) {
                ull wj = wp[j];
                acc[j][0] = fma2(wj, pv0, acc[j][0]);
                acc[j][1] = fma2(wj, pv1, acc[j][1]);
                acc[j][2] = fma2(wj, pv2, acc[j][2]);
                acc[j][3] = fma2(wj, pv3, acc[j][3]);
            }
        }

        int c = g * 4 + o_out;
#pragma unroll
        for (int q = 0; q < 4; q++) {
            ull part = 0ull;
#pragma unroll
            for (int j = 0; j < 8; j++)
                part = fma2(att2s[(n0 + j) * 65 + pp0 + q], acc[j][q], part);
            part = add2(part, __shfl_xor_sync(0xffffffffu, part, 1));
            part = add2(part, __shfl_xor_sync(0xffffffffu, part, 2));
            if ((tid & 3) == 0) {
                ull ufc2 = patch2s[(o_out * 9 + 4) * 64 + pp0 + q];
                ull ga2  = dup2(ga1[c]);
                ull sc2  = dup2(g_sca[bi * 64 + c]);
                ull z2 = mul2(fma2(ga2, part, ufc2), sc2);
                float2 zo;
                asm("mov.b64 {%0, %1}, %2;" : "=f"(zo.x), "=f"(zo.y) : "l"(z2));
                *(float2*)&g_z[((size_t)bi * 64 + c) * HWPIX + hw0 + 2 * (pp0 + q)] = zo;
            }
        }
    }
}

// ---------------- K7: fused conv3+res + LN2 + FFN + res --------------------
#define FFN_SMEM ((64 * 33 * 2 + 64 * 64 + 64 * 128 + 64 * 64 + 8 * 33 * 2) * 4)
__global__ void ffn_fused_kernel(const float* __restrict__ inp,
                                 const float* __restrict__ w3, const float* __restrict__ b3,
                                 const float* __restrict__ beta,
                                 const float* __restrict__ ln2w, const float* __restrict__ ln2b,
                                 const float* __restrict__ w4, const float* __restrict__ b4,
                                 const float* __restrict__ w5, const float* __restrict__ b5,
                                 const float* __restrict__ gamma, float* __restrict__ out) {
    extern __shared__ float fs[];
    float* B1   = fs;                      // [64][33]  z, then xn
    float* gs   = B1 + 64 * 33;            // [64][33]
    float* w3T  = gs + 64 * 33;            // [ic][oc] 4096
    float* w4T  = w3T + 4096;              // [ic][j] 64x128
    float* w5T  = w4T + 8192;              // [j][oc] 4096
    float* red1 = w5T + 4096;              // [8][33]
    float* red2 = red1 + 8 * 33;
    int tid = threadIdx.x;
    int w = tid >> 5, lane = tid & 31;
    for (int i = tid; i < 4096; i += 256) {
        int ic = i >> 6, oc = i & 63;
        w3T[i] = w3[oc * 64 + ic];
    }
    for (int i = tid; i < 8192; i += 256) {
        int ic = i >> 7, j = i & 127;
        w4T[i] = w4[j * 64 + ic];
    }
    for (int i = tid; i < 4096; i += 256) {
        int j = i >> 6, oc = i & 63;
        w5T[i] = w5[oc * 64 + j];
    }
    int tile = blockIdx.x;
    int bi = tile / (HWPIX / 32);
    int hw0 = (tile % (HWPIX / 32)) * 32;
    // stage z
    const float* zsrc = g_z + ((size_t)bi * 64 + 8 * w) * HWPIX + hw0 + lane;
#pragma unroll
    for (int j = 0; j < 8; j++) B1[(8 * w + j) * 33 + lane] = zsrc[j * HWPIX];
    __syncthreads();
    // conv3 + beta residual -> yv
    float yv[8];
    {
        float acc[8];
#pragma unroll
        for (int j = 0; j < 8; j++) acc[j] = b3[8 * w + j];
        for (int ic = 0; ic < 64; ic++) {
            float zv = B1[ic * 33 + lane];
            float4 wa = *(const float4*)&w3T[ic * 64 + 8 * w];
            float4 wb = *(const float4*)&w3T[ic * 64 + 8 * w + 4];
            acc[0] += wa.x * zv; acc[1] += wa.y * zv;
            acc[2] += wa.z * zv; acc[3] += wa.w * zv;
            acc[4] += wb.x * zv; acc[5] += wb.y * zv;
            acc[6] += wb.z * zv; acc[7] += wb.w * zv;
        }
        const float* rsd = inp + ((size_t)bi * 64 + 8 * w) * HWPIX + hw0 + lane;
#pragma unroll
        for (int j = 0; j < 8; j++)
            yv[j] = rsd[j * HWPIX] + acc[j] * beta[8 * w + j];
    }
    // LN2 stats
    float s = 0.f;
#pragma unroll
    for (int j = 0; j < 8; j++) s += yv[j];
    red1[w * 33 + lane] = s;
    __syncthreads();
    float mu = 0.f;
#pragma unroll
    for (int i = 0; i < 8; i++) mu += red1[i * 33 + lane];
    mu *= (1.f / 64.f);
    float q = 0.f;
#pragma unroll
    for (int j = 0; j < 8; j++) { float d = yv[j] - mu; q += d * d; }
    red2[w * 33 + lane] = q;
    __syncthreads();
    float var = 0.f;
#pragma unroll
    for (int i = 0; i < 8; i++) var += red2[i * 33 + lane];
    float rinv = rsqrtf(var * (1.f / 64.f) + 1e-6f);
    // xn -> B1 (z fully consumed; last sync guarantees safety)
#pragma unroll
    for (int j = 0; j < 8; j++) {
        int c = 8 * w + j;
        B1[c * 33 + lane] = (yv[j] - mu) * rinv * ln2w[c] + ln2b[c];
    }
    __syncthreads();
    // conv4 + gate: warp w -> pair j in 8w..8w+8
    {
        float a[8], b2[8];
#pragma unroll
        for (int j = 0; j < 8; j++) { a[j] = b4[8 * w + j]; b2[j] = b4[8 * w + j + 64]; }
        for (int ic = 0; ic < 64; ic++) {
            float xv = B1[ic * 33 + lane];
            float4 wa = *(const float4*)&w4T[ic * 128 + 8 * w];
            float4 wb = *(const float4*)&w4T[ic * 128 + 8 * w + 4];
            float4 wc = *(const float4*)&w4T[ic * 128 + 64 + 8 * w];
            float4 wd = *(const float4*)&w4T[ic * 128 + 64 + 8 * w + 4];
            a[0] += wa.x * xv; a[1] += wa.y * xv; a[2] += wa.z * xv; a[3] += wa.w * xv;
            a[4] += wb.x * xv; a[5] += wb.y * xv; a[6] += wb.z * xv; a[7] += wb.w * xv;
            b2[0] += wc.x * xv; b2[1] += wc.y * xv; b2[2] += wc.z * xv; b2[3] += wc.w * xv;
            b2[4] += wd.x * xv; b2[5] += wd.y * xv; b2[6] += wd.z * xv; b2[7] += wd.w * xv;
        }
#pragma unroll
        for (int j = 0; j < 8; j++) gs[(8 * w + j) * 33 + lane] = a[j] * b2[j];
    }
    __syncthreads();
    // conv5 + gamma residual
    {
        float acc[8];
#pragma unroll
        for (int j = 0; j < 8; j++) acc[j] = b5[8 * w + j];
        for (int j = 0; j < 64; j++) {
            float gv = gs[j * 33 + lane];
            float4 wa = *(const float4*)&w5T[j * 64 + 8 * w];
            float4 wb = *(const float4*)&w5T[j * 64 + 8 * w + 4];
            acc[0] += wa.x * gv; acc[1] += wa.y * gv;
            acc[2] += wa.z * gv; acc[3] += wa.w * gv;
            acc[4] += wb.x * gv; acc[5] += wb.y * gv;
            acc[6] += wb.z * gv; acc[7] += wb.w * gv;
        }
        float* dst = out + ((size_t)bi * 64 + 8 * w) * HWPIX + hw0 + lane;
#pragma unroll
        for (int j = 0; j < 8; j++)
            dst[j * HWPIX] = yv[j] + acc[j] * gamma[8 * w + j];
    }
}

// ---------------------------------------------------------------------------
extern "C" void kernel_launch(void* const* d_in, const int* in_sizes, int n_in,
                              void* d_out, int out_size) {
    const float* inp      = (const float*)d_in[0];
    const float* ln1_w    = (const float*)d_in[1];
    const float* ln1_b    = (const float*)d_in[2];
    const float* ln2_w    = (const float*)d_in[3];
    const float* ln2_b    = (const float*)d_in[4];
    const float* sca_w    = (const float*)d_in[5];
    const float* sca_b    = (const float*)d_in[6];
    const float* c11a_w   = (const float*)d_in[7];
    const float* c11a_b   = (const float*)d_in[8];
    const float* c11b_w   = (const float*)d_in[9];
    const float* c11b_b   = (const float*)d_in[10];
    const float* c2a_w    = (const float*)d_in[11];
    const float* c2a_b    = (const float*)d_in[12];
    const float* c2b_w    = (const float*)d_in[13];
    const float* c2b_b    = (const float*)d_in[14];
    const float* conv3_w  = (const float*)d_in[15];
    const float* conv3_b  = (const float*)d_in[16];
    const float* conv4_w  = (const float*)d_in[17];
    const float* conv4_b  = (const float*)d_in[18];
    const float* conv5_w  = (const float*)d_in[19];
    const float* conv5_b  = (const float*)d_in[20];
    const float* kb_w     = (const float*)d_in[21];
    const float* kb_b     = (const float*)d_in[22];
    const float* ga1      = (const float*)d_in[23];
    const float* attgamma = (const float*)d_in[24];
    const float* beta     = (const float*)d_in[25];
    const float* gamma    = (const float*)d_in[26];
    float* out = (float*)d_out;

    static int attr_done = 0;
    if (!attr_done) {
        cudaFuncSetAttribute(uf_kernel, cudaFuncAttributeMaxDynamicSharedMemorySize, UF_SMEM);
        cudaFuncSetAttribute(kba_kernel, cudaFuncAttributeMaxDynamicSharedMemorySize, KBA_SMEM_BYTES);
        cudaFuncSetAttribute(ffn_fused_kernel, cudaFuncAttributeMaxDynamicSharedMemorySize, FFN_SMEM);
        attr_done = 1;
    }

    kbw_prep_kernel<<<(16 * 37 * 128 + 255) / 256, 256>>>(kb_w, kb_b);
    ln1_c11a_kernel<<<NPIX / 32, 256>>>(inp, ln1_w, ln1_b, c11a_w, c11a_b);
    mean_kernel<<<NB * CCH, 512>>>();
    sca_kernel<<<1, 128>>>(sca_w, sca_b);
    att_kernel<<<NPIX / 32, 256>>>(c2a_w, c2a_b, c2b_w, c2b_b, attgamma);
    uf_kernel<<<NPIX / 32, 256, UF_SMEM>>>(c11b_w, c11b_b);
    {
        dim3 grid(NPIX / 128, 4);
        kba_kernel<<<grid, 256, KBA_SMEM_BYTES>>>(ga1);
    }
    ffn_fused_kernel<<<NPIX / 32, 256, FFN_SMEM>>>(inp, conv3_w, conv3_b, beta,
                                                   ln2_w, ln2_b, conv4_w, conv4_b,
                                                   conv5_w, conv5_b, gamma, out);
}

// round 4
// speedup vs baseline: 1.8162x; 1.8162x over previous
#include <cuda_runtime.h>

#define HT 160
#define WDx 160
#define HWPIX 25600
#define NB 2
#define NPIX (NB * HWPIX)
#define CCH 64
#define NSETC 32

typedef unsigned long long ull;

__device__ __forceinline__ ull pack2(float a, float b) {
    ull r; asm("mov.b64 %0, {%1, %2};" : "=l"(r) : "f"(a), "f"(b)); return r;
}
__device__ __forceinline__ ull dup2(float a) {
    ull r; asm("mov.b64 %0, {%1, %1};" : "=l"(r) : "f"(a)); return r;
}
__device__ __forceinline__ ull fma2(ull a, ull b, ull c) {
    ull r; asm("fma.rn.f32x2 %0, %1, %2, %3;" : "=l"(r) : "l"(a), "l"(b), "l"(c)); return r;
}
__device__ __forceinline__ ull add2(ull a, ull b) {
    ull r; asm("add.rn.f32x2 %0, %1, %2;" : "=l"(r) : "l"(a), "l"(b)); return r;
}
__device__ __forceinline__ ull mul2(ull a, ull b) {
    ull r; asm("mul.rn.f32x2 %0, %1, %2;" : "=l"(r) : "l"(a), "l"(b)); return r;
}

// ---------------- scratch (device globals) ---------------------------------
__device__ float g_x[NPIX * CCH];      // LN1 output
__device__ float g_att[NPIX * NSETC];  // attention maps
__device__ float g_u1[NPIX * CCH];     // conv1x1a output
__device__ float g_uf[NPIX * CCH];     // 5x5 grouped conv output
__device__ float g_z[NPIX * CCH];      // KBA output (pre-sca)
__device__ float g_y[NPIX * CCH];      // mid residual
__device__ float g_xmean[NB * CCH];
__device__ float g_sca[NB * CCH];
__device__ ull   g_kbwT2[16 * 37 * 128]; // dup-pair weights, [g][k][j*16+mb]

// ---------------- K0: prep kb weights (conflict-free interleave) -----------
__global__ void kbw_prep_kernel(const float* __restrict__ kb_w,
                                const float* __restrict__ kb_b) {
    int idx = blockIdx.x * 256 + threadIdx.x;
    if (idx >= 16 * 37 * 128) return;
    int slot = idx & 127;
    int k = (idx >> 7) % 37;
    int g = idx / (37 * 128);
    int j = slot >> 4, mb = slot & 15;
    int m = mb * 8 + j;
    int o = m >> 5, n = m & 31;
    float v = (k < 36) ? kb_w[n * 2304 + g * 144 + o * 36 + k]
                       : kb_b[n * 64 + g * 4 + o];
    g_kbwT2[idx] = dup2(v);
}

// ---------------- K1: LayerNorm over channels (per pixel) ------------------
__global__ void ln1_kernel(const float* __restrict__ inp,
                           const float* __restrict__ w,
                           const float* __restrict__ b) {
    int p = blockIdx.x * blockDim.x + threadIdx.x;
    if (p >= NPIX) return;
    int bi = p / HWPIX, hw = p - bi * HWPIX;
    const float* src = inp + (size_t)bi * CCH * HWPIX + hw;
    float v[64];
    float s = 0.f;
#pragma unroll
    for (int c = 0; c < 64; c++) { v[c] = src[c * HWPIX]; s += v[c]; }
    float mu = s * (1.f / 64.f);
    float q = 0.f;
#pragma unroll
    for (int c = 0; c < 64; c++) { float d = v[c] - mu; q += d * d; }
    float rinv = rsqrtf(q * (1.f / 64.f) + 1e-6f);
    float* dst = g_x + (size_t)bi * CCH * HWPIX + hw;
#pragma unroll
    for (int c = 0; c < 64; c++)
        dst[c * HWPIX] = (v[c] - mu) * rinv * w[c] + b[c];
}

// ---------------- K2: per-(b,c) spatial mean of g_x ------------------------
__global__ void mean_kernel() {
    int bc = blockIdx.x;
    const float* src = g_x + (size_t)bc * HWPIX;
    float s = 0.f;
    for (int i = threadIdx.x; i < HWPIX; i += blockDim.x) s += src[i];
#pragma unroll
    for (int o = 16; o > 0; o >>= 1) s += __shfl_down_sync(0xffffffffu, s, o);
    __shared__ float red[16];
    if ((threadIdx.x & 31) == 0) red[threadIdx.x >> 5] = s;
    __syncthreads();
    if (threadIdx.x == 0) {
        float t = 0.f;
        for (int i = 0; i < (int)(blockDim.x >> 5); i++) t += red[i];
        g_xmean[bc] = t * (1.f / HWPIX);
    }
}

// ---------------- K3: sca = 1x1 conv on pooled means -----------------------
__global__ void sca_kernel(const float* __restrict__ w, const float* __restrict__ b) {
    int t = threadIdx.x;
    if (t < NB * CCH) {
        int bi = t >> 6, c = t & 63;
        float a = b[c];
#pragma unroll
        for (int k = 0; k < 64; k++) a += w[c * 64 + k] * g_xmean[bi * 64 + k];
        g_sca[t] = a;
    }
}

// ---------------- K4: attention path (grouped3x3 + gate + 1x1) -------------
__global__ void att_kernel(const float* __restrict__ c2a_w, const float* __restrict__ c2a_b,
                           const float* __restrict__ c2b_w, const float* __restrict__ c2b_b,
                           const float* __restrict__ attgamma) {
    __shared__ float wa[32 * 18];
    __shared__ float ba[32];
    __shared__ float wbT[16 * 32]; // [j][n]
    __shared__ float bb[32], ag[32];
    for (int i = threadIdx.x; i < 576; i += blockDim.x) wa[i] = c2a_w[i];
    if (threadIdx.x < 32) {
        ba[threadIdx.x] = c2a_b[threadIdx.x];
        bb[threadIdx.x] = c2b_b[threadIdx.x];
        ag[threadIdx.x] = attgamma[threadIdx.x];
    }
    for (int i = threadIdx.x; i < 512; i += blockDim.x) {
        int j = i >> 5, n = i & 31;
        wbT[i] = c2b_w[n * 16 + j];
    }
    __syncthreads();
    int p = blockIdx.x * blockDim.x + threadIdx.x;
    if (p >= NPIX) return;
    int bi = p / HWPIX, hw = p - bi * HWPIX;
    int h = hw / WDx, w = hw - h * WDx;
    const float* xb = g_x + (size_t)bi * CCH * HWPIX;
    float att_acc[32];
#pragma unroll
    for (int n = 0; n < 32; n++) att_acc[n] = 0.f;
#pragma unroll 4
    for (int j = 0; j < 16; j++) {
        float t0 = ba[j], t1 = ba[j + 16];
#pragma unroll
        for (int l = 0; l < 2; l++) {
            const float* xp0 = xb + (2 * j + l) * HWPIX;
            const float* xp1 = xb + (2 * (j + 16) + l) * HWPIX;
#pragma unroll
            for (int dy = 0; dy < 3; dy++) {
                int hy = h + dy - 1;
                bool vy = ((unsigned)hy < HT);
#pragma unroll
                for (int dx = 0; dx < 3; dx++) {
                    int wx = w + dx - 1;
                    bool ok = vy && ((unsigned)wx < WDx);
                    int off = hy * WDx + wx;
                    float x0 = ok ? xp0[off] : 0.f;
                    float x1 = ok ? xp1[off] : 0.f;
                    t0 += wa[j * 18 + l * 9 + dy * 3 + dx] * x0;
                    t1 += wa[(j + 16) * 18 + l * 9 + dy * 3 + dx] * x1;
                }
            }
        }
        float gj = t0 * t1;
        const float4* wp = (const float4*)&wbT[j * 32];
#pragma unroll
        for (int n4 = 0; n4 < 8; n4++) {
            float4 wv = wp[n4];
            att_acc[4 * n4 + 0] += wv.x * gj;
            att_acc[4 * n4 + 1] += wv.y * gj;
            att_acc[4 * n4 + 2] += wv.z * gj;
            att_acc[4 * n4 + 3] += wv.w * gj;
        }
    }
    float* dst = g_att + (size_t)bi * NSETC * HWPIX + hw;
#pragma unroll
    for (int n = 0; n < 32; n++)
        dst[n * HWPIX] = (att_acc[n] + bb[n]) * ag[n];
}

// ---------------- K5: 1x1 conv 64->64 (c11a) on g_x -> g_u1 ----------------
__global__ void conv1x1_u1(const float* __restrict__ w, const float* __restrict__ b) {
    __shared__ float ws[4096];
    __shared__ float bs[64];
    for (int i = threadIdx.x; i < 4096; i += blockDim.x) ws[i] = w[i];
    if (threadIdx.x < 64) bs[threadIdx.x] = b[threadIdx.x];
    __syncthreads();
    int p = blockIdx.x * blockDim.x + threadIdx.x;
    if (p >= NPIX) return;
    int bi = p / HWPIX, hw = p - bi * HWPIX;
    const float* src = g_x + (size_t)bi * CCH * HWPIX + hw;
    float xin[64];
#pragma unroll
    for (int i = 0; i < 64; i++) xin[i] = src[i * HWPIX];
    float* dst = g_u1 + (size_t)bi * CCH * HWPIX + hw;
#pragma unroll 4
    for (int o = 0; o < 64; o++) {
        float a = bs[o];
        const float4* wp = (const float4*)&ws[o * 64];
#pragma unroll
        for (int i4 = 0; i4 < 16; i4++) {
            float4 wv = wp[i4];
            a += wv.x * xin[4 * i4] + wv.y * xin[4 * i4 + 1] +
                 wv.z * xin[4 * i4 + 2] + wv.w * xin[4 * i4 + 3];
        }
        dst[o * HWPIX] = a;
    }
}

// ---------------- K6: grouped 5x5 conv (16 groups of 4) g_u1 -> g_uf -------
__global__ void uf_kernel(const float* __restrict__ w5, const float* __restrict__ b5) {
    __shared__ float ws[6400]; // [g][ic][kk][oc]
    __shared__ float bs[64];
    for (int i = threadIdx.x; i < 6400; i += blockDim.x) {
        int oc = i & 3;
        int r = i >> 2;
        int g = r / 100;
        int r2 = r - g * 100;
        int ic = r2 / 25, kk = r2 - ic * 25;
        ws[i] = w5[((g * 4 + oc) * 4 + ic) * 25 + kk];
    }
    if (threadIdx.x < 64) bs[threadIdx.x] = b5[threadIdx.x];
    __syncthreads();
    int p = blockIdx.x * blockDim.x + threadIdx.x;
    if (p >= NPIX) return;
    int bi = p / HWPIX, hw = p - bi * HWPIX;
    int h = hw / WDx, w = hw - h * WDx;
    const float* ub = g_u1 + (size_t)bi * CCH * HWPIX;
    float* dst = g_uf + (size_t)bi * CCH * HWPIX + hw;
    for (int g = 0; g < 16; g++) {
        float a0 = bs[g * 4 + 0], a1 = bs[g * 4 + 1], a2 = bs[g * 4 + 2], a3 = bs[g * 4 + 3];
        const float* gin = ub + (g * 4) * HWPIX;
#pragma unroll
        for (int dy = 0; dy < 5; dy++) {
            int hy = h + dy - 2;
            bool vy = ((unsigned)hy < HT);
#pragma unroll
            for (int dx = 0; dx < 5; dx++) {
                int wx = w + dx - 2;
                bool ok = vy && ((unsigned)wx < WDx);
                int off = hy * WDx + wx;
                int kk = dy * 5 + dx;
#pragma unroll
                for (int ic = 0; ic < 4; ic++) {
                    float v = ok ? gin[ic * HWPIX + off] : 0.f;
                    const float4 wv = *(const float4*)&ws[(g * 100 + ic * 25 + kk) * 4];
                    a0 += wv.x * v; a1 += wv.y * v; a2 += wv.z * v; a3 += wv.w * v;
                }
            }
        }
        dst[(g * 4 + 0) * HWPIX] = a0;
        dst[(g * 4 + 1) * HWPIX] = a1;
        dst[(g * 4 + 2) * HWPIX] = a2;
        dst[(g * 4 + 3) * HWPIX] = a3;
    }
}

// ---------------- K7: fused KBA (f32x2, 4 groups/block, conflict-free) -----
#define KBA_SMEM_BYTES (37 * 128 * 8 + 37 * 64 * 8 + 32 * 65 * 8)
__global__ void kba_kernel(const float* __restrict__ ga1) {
    extern __shared__ char smem[];
    ull* Ws2     = (ull*)smem;                                // [37][128] interleaved
    ull* patch2s = (ull*)(smem + 37 * 128 * 8);               // [37][64]
    ull* att2s   = (ull*)(smem + 37 * 128 * 8 + 37 * 64 * 8); // [32][65]

    int tid = threadIdx.x;
    int bi  = blockIdx.x / (HWPIX / 128);
    int hw0 = (blockIdx.x % (HWPIX / 128)) * 128;
    int g0  = blockIdx.y * 4;

    for (int idx = tid; idx < 32 * 64; idx += 256) {
        int n = idx >> 6, pp = idx & 63;
        const float2 v = *(const float2*)&g_att[((size_t)bi * 32 + n) * HWPIX + hw0 + 2 * pp];
        att2s[n * 65 + pp] = pack2(v.x, v.y);
    }

    int m_blk = tid & 15;
    int pp0   = (tid >> 4) * 4;
    int o_out = m_blk >> 2;
    int n0    = (m_blk & 3) * 8;

    for (int gi = 0; gi < 4; gi++) {
        int g = g0 + gi;
        __syncthreads();
        const ull* wsrc = g_kbwT2 + (size_t)g * 37 * 128;
        for (int idx = tid; idx < 37 * 128; idx += 256) Ws2[idx] = wsrc[idx];
        for (int idx = tid; idx < 36 * 64; idx += 256) {
            int k = idx >> 6, pp = idx & 63;
            int ci = k / 9, kk = k - ci * 9;
            int dy = kk / 3, dx = kk - dy * 3;
            const float* ufc = g_uf + ((size_t)bi * 64 + g * 4 + ci) * HWPIX;
            float v0, v1;
            {
                int p = hw0 + 2 * pp;
                int h = p / WDx, w = p - h * WDx;
                int hy = h + dy - 1, wx = w + dx - 1;
                v0 = ((unsigned)hy < HT && (unsigned)wx < WDx) ? ufc[hy * WDx + wx] : 0.f;
            }
            {
                int p = hw0 + 2 * pp + 1;
                int h = p / WDx, w = p - h * WDx;
                int hy = h + dy - 1, wx = w + dx - 1;
                v1 = ((unsigned)hy < HT && (unsigned)wx < WDx) ? ufc[hy * WDx + wx] : 0.f;
            }
            patch2s[idx] = pack2(v0, v1);
        }
        if (tid < 64) patch2s[36 * 64 + tid] = pack2(1.f, 1.f);
        __syncthreads();

        ull acc[8][4];
#pragma unroll
        for (int j = 0; j < 8; j++)
#pragma unroll
            for (int q = 0; q < 4; q++) acc[j][q] = 0ull;

        for (int k = 0; k < 37; k++) {
            const ull* pvp = &patch2s[k * 64 + pp0];
            ull pv0 = pvp[0], pv1 = pvp[1], pv2 = pvp[2], pv3 = pvp[3];
            const ull* wp = &Ws2[k * 128];
#pragma unroll
            for (int j = 0; j < 8; j++) {
                ull wj = wp[j * 16 + m_blk];   // conflict-free: bank pair 2*m_blk
                acc[j][0] = fma2(wj, pv0, acc[j][0]);
                acc[j][1] = fma2(wj, pv1, acc[j][1]);
                acc[j][2] = fma2(wj, pv2, acc[j][2]);
                acc[j][3] = fma2(wj, pv3, acc[j][3]);
            }
        }

        int c = g * 4 + o_out;
#pragma unroll
        for (int q = 0; q < 4; q++) {
            ull part = 0ull;
#pragma unroll
            for (int j = 0; j < 8; j++)
                part = fma2(att2s[(n0 + j) * 65 + pp0 + q], acc[j][q], part);
            part = add2(part, __shfl_xor_sync(0xffffffffu, part, 1));
            part = add2(part, __shfl_xor_sync(0xffffffffu, part, 2));
            if ((tid & 3) == 0) {
                ull ufc2 = patch2s[(o_out * 9 + 4) * 64 + pp0 + q];
                ull ga2  = dup2(ga1[c]);
                ull z2 = fma2(ga2, part, ufc2);   // sca folded into conv3
                float2 zo;
                asm("mov.b64 {%0, %1}, %2;" : "=f"(zo.x), "=f"(zo.y) : "l"(z2));
                *(float2*)&g_z[((size_t)bi * 64 + c) * HWPIX + hw0 + 2 * (pp0 + q)] = zo;
            }
        }
    }
}

// ---------------- K8: conv3 (1x1, input*sca) + beta residual -> g_y --------
__global__ void conv3_res_kernel(const float* __restrict__ inp,
                                 const float* __restrict__ w,
                                 const float* __restrict__ b,
                                 const float* __restrict__ beta) {
    __shared__ float ws[4096];
    __shared__ float bs[64];
    __shared__ float ss[64];
    int bi0 = (blockIdx.x * (int)blockDim.x) / HWPIX;
    for (int i = threadIdx.x; i < 4096; i += blockDim.x) ws[i] = w[i];
    if (threadIdx.x < 64) {
        bs[threadIdx.x] = b[threadIdx.x];
        ss[threadIdx.x] = g_sca[bi0 * 64 + threadIdx.x];
    }
    __syncthreads();
    int p = blockIdx.x * blockDim.x + threadIdx.x;
    if (p >= NPIX) return;
    int bi = p / HWPIX, hw = p - bi * HWPIX;
    const float* src = g_z + (size_t)bi * CCH * HWPIX + hw;
    const float* rsd = inp + (size_t)bi * CCH * HWPIX + hw;
    float xin[64];
#pragma unroll
    for (int i = 0; i < 64; i++) xin[i] = src[i * HWPIX] * ss[i];
    float* dst = g_y + (size_t)bi * CCH * HWPIX + hw;
#pragma unroll 4
    for (int o = 0; o < 64; o++) {
        float a = bs[o];
        const float4* wp = (const float4*)&ws[o * 64];
#pragma unroll
        for (int i4 = 0; i4 < 16; i4++) {
            float4 wv = wp[i4];
            a += wv.x * xin[4 * i4] + wv.y * xin[4 * i4 + 1] +
                 wv.z * xin[4 * i4 + 2] + wv.w * xin[4 * i4 + 3];
        }
        dst[o * HWPIX] = rsd[o * HWPIX] + a * beta[o];
    }
}

// ---------------- K9: LN2 + FFN (conv4, gate, conv5) + gamma residual ------
__global__ void ffn_kernel(const float* __restrict__ ln2w, const float* __restrict__ ln2b,
                           const float* __restrict__ w4, const float* __restrict__ b4,
                           const float* __restrict__ w5, const float* __restrict__ b5,
                           const float* __restrict__ gamma, float* __restrict__ out) {
    __shared__ float ws[12288]; // [0:8192) w4 [j][i], [8192:12288) w5T [j][o]
    for (int i = threadIdx.x; i < 8192; i += blockDim.x) ws[i] = w4[i];
    for (int i = threadIdx.x; i < 4096; i += blockDim.x) {
        int j = i >> 6, o = i & 63;
        ws[8192 + i] = w5[o * 64 + j];
    }
    __syncthreads();
    int p = blockIdx.x * blockDim.x + threadIdx.x;
    if (p >= NPIX) return;
    int bi = p / HWPIX, hw = p - bi * HWPIX;
    const float* yb = g_y + (size_t)bi * CCH * HWPIX + hw;
    float v[64];
    float s = 0.f;
#pragma unroll
    for (int c = 0; c < 64; c++) { v[c] = yb[c * HWPIX]; s += v[c]; }
    float mu = s * (1.f / 64.f);
    float q = 0.f;
#pragma unroll
    for (int c = 0; c < 64; c++) { float d = v[c] - mu; q += d * d; }
    float rinv = rsqrtf(q * (1.f / 64.f) + 1e-6f);
    float xn[64];
#pragma unroll
    for (int c = 0; c < 64; c++) xn[c] = (v[c] - mu) * rinv * ln2w[c] + ln2b[c];
    float acc[64];
#pragma unroll
    for (int o = 0; o < 64; o++) acc[o] = 0.f;
    for (int j = 0; j < 64; j++) {
        float a = b4[j], bb = b4[j + 64];
        const float4* wpa = (const float4*)&ws[j * 64];
        const float4* wpb = (const float4*)&ws[(j + 64) * 64];
#pragma unroll
        for (int i4 = 0; i4 < 16; i4++) {
            float4 wva = wpa[i4];
            float4 wvb = wpb[i4];
            a  += wva.x * xn[4 * i4] + wva.y * xn[4 * i4 + 1] + wva.z * xn[4 * i4 + 2] + wva.w * xn[4 * i4 + 3];
            bb += wvb.x * xn[4 * i4] + wvb.y * xn[4 * i4 + 1] + wvb.z * xn[4 * i4 + 2] + wvb.w * xn[4 * i4 + 3];
        }
        float gj = a * bb;
        const float4* wp5 = (const float4*)&ws[8192 + j * 64];
#pragma unroll
        for (int o4 = 0; o4 < 16; o4++) {
            float4 wv = wp5[o4];
            acc[4 * o4 + 0] += wv.x * gj;
            acc[4 * o4 + 1] += wv.y * gj;
            acc[4 * o4 + 2] += wv.z * gj;
            acc[4 * o4 + 3] += wv.w * gj;
        }
    }
    float* dst = out + (size_t)bi * CCH * HWPIX + hw;
#pragma unroll
    for (int o = 0; o < 64; o++)
        dst[o * HWPIX] = v[o] + (acc[o] + b5[o]) * gamma[o];
}

// ---------------------------------------------------------------------------
extern "C" void kernel_launch(void* const* d_in, const int* in_sizes, int n_in,
                              void* d_out, int out_size) {
    const float* inp      = (const float*)d_in[0];
    const float* ln1_w    = (const float*)d_in[1];
    const float* ln1_b    = (const float*)d_in[2];
    const float* ln2_w    = (const float*)d_in[3];
    const float* ln2_b    = (const float*)d_in[4];
    const float* sca_w    = (const float*)d_in[5];
    const float* sca_b    = (const float*)d_in[6];
    const float* c11a_w   = (const float*)d_in[7];
    const float* c11a_b   = (const float*)d_in[8];
    const float* c11b_w   = (const float*)d_in[9];
    const float* c11b_b   = (const float*)d_in[10];
    const float* c2a_w    = (const float*)d_in[11];
    const float* c2a_b    = (const float*)d_in[12];
    const float* c2b_w    = (const float*)d_in[13];
    const float* c2b_b    = (const float*)d_in[14];
    const float* conv3_w  = (const float*)d_in[15];
    const float* conv3_b  = (const float*)d_in[16];
    const float* conv4_w  = (const float*)d_in[17];
    const float* conv4_b  = (const float*)d_in[18];
    const float* conv5_w  = (const float*)d_in[19];
    const float* conv5_b  = (const float*)d_in[20];
    const float* kb_w     = (const float*)d_in[21];
    const float* kb_b     = (const float*)d_in[22];
    const float* ga1      = (const float*)d_in[23];
    const float* attgamma = (const float*)d_in[24];
    const float* beta     = (const float*)d_in[25];
    const float* gamma    = (const float*)d_in[26];
    float* out = (float*)d_out;

    cudaFuncSetAttribute(kba_kernel, cudaFuncAttributeMaxDynamicSharedMemorySize,
                         KBA_SMEM_BYTES);

    // order chosen so uf_kernel is the 4th launch (ncu captures launch #4)
    kbw_prep_kernel<<<(16 * 37 * 128 + 255) / 256, 256>>>(kb_w, kb_b);
    ln1_kernel<<<NPIX / 256, 256>>>(inp, ln1_w, ln1_b);
    conv1x1_u1<<<NPIX / 256, 256>>>(c11a_w, c11a_b);
    uf_kernel<<<NPIX / 256, 256>>>(c11b_w, c11b_b);
    att_kernel<<<NPIX / 256, 256>>>(c2a_w, c2a_b, c2b_w, c2b_b, attgamma);
    {
        dim3 grid(NPIX / 128, 4);
        kba_kernel<<<grid, 256, KBA_SMEM_BYTES>>>(ga1);
    }
    mean_kernel<<<NB * CCH, 512>>>();
    sca_kernel<<<1, 128>>>(sca_w, sca_b);
    conv3_res_kernel<<<NPIX / 256, 256>>>(inp, conv3_w, conv3_b, beta);
    ffn_kernel<<<NPIX / 128, 128>>>(ln2_w, ln2_b, conv4_w, conv4_b,
                                    conv5_w, conv5_b, gamma, out);
}

// round 5
// speedup vs baseline: 1.8966x; 1.0443x over previous
#include <cuda_runtime.h>

#define HT 160
#define WDx 160
#define HWPIX 25600
#define NB 2
#define NPIX (NB * HWPIX)
#define CCH 64
#define NSETC 32

typedef unsigned long long ull;

__device__ __forceinline__ ull pack2(float a, float b) {
    ull r; asm("mov.b64 %0, {%1, %2};" : "=l"(r) : "f"(a), "f"(b)); return r;
}
__device__ __forceinline__ ull dup2(float a) {
    ull r; asm("mov.b64 %0, {%1, %1};" : "=l"(r) : "f"(a)); return r;
}
__device__ __forceinline__ ull fma2(ull a, ull b, ull c) {
    ull r; asm("fma.rn.f32x2 %0, %1, %2, %3;" : "=l"(r) : "l"(a), "l"(b), "l"(c)); return r;
}
__device__ __forceinline__ ull add2(ull a, ull b) {
    ull r; asm("add.rn.f32x2 %0, %1, %2;" : "=l"(r) : "l"(a), "l"(b)); return r;
}
__device__ __forceinline__ ull mul2(ull a, ull b) {
    ull r; asm("mul.rn.f32x2 %0, %1, %2;" : "=l"(r) : "l"(a), "l"(b)); return r;
}

// ---------------- scratch (device globals) ---------------------------------
__device__ float g_x[NPIX * CCH];      // LN1 output
__device__ float g_att[NPIX * NSETC];  // attention maps
__device__ float g_u1[NPIX * CCH];     // conv1x1a output
__device__ float g_uf[NPIX * CCH];     // 5x5 grouped conv output
__device__ float g_z[NPIX * CCH];      // KBA output (pre-sca)
__device__ float g_y[NPIX * CCH];      // mid residual
__device__ float g_gate[NPIX * CCH];   // FFN gate output (64 ch)
__device__ float g_xmean[NB * CCH];
__device__ float g_sca[NB * CCH];
__device__ ull   g_kbwT2[16 * 37 * 128]; // dup-pair weights, [g][k][j*16+mb]

// ---------------- K0: prep kb weights (conflict-free interleave) -----------
__global__ void kbw_prep_kernel(const float* __restrict__ kb_w,
                                const float* __restrict__ kb_b) {
    int idx = blockIdx.x * 256 + threadIdx.x;
    if (idx >= 16 * 37 * 128) return;
    int slot = idx & 127;
    int k = (idx >> 7) % 37;
    int g = idx / (37 * 128);
    int j = slot >> 4, mb = slot & 15;
    int m = mb * 8 + j;
    int o = m >> 5, n = m & 31;
    float v = (k < 36) ? kb_w[n * 2304 + g * 144 + o * 36 + k]
                       : kb_b[n * 64 + g * 4 + o];
    g_kbwT2[idx] = dup2(v);
}

// ---------------- K1: LayerNorm over channels (per pixel) ------------------
__global__ void ln1_kernel(const float* __restrict__ inp,
                           const float* __restrict__ w,
                           const float* __restrict__ b) {
    int p = blockIdx.x * blockDim.x + threadIdx.x;
    if (p >= NPIX) return;
    int bi = p / HWPIX, hw = p - bi * HWPIX;
    const float* src = inp + (size_t)bi * CCH * HWPIX + hw;
    float v[64];
    float s = 0.f;
#pragma unroll
    for (int c = 0; c < 64; c++) { v[c] = src[c * HWPIX]; s += v[c]; }
    float mu = s * (1.f / 64.f);
    float q = 0.f;
#pragma unroll
    for (int c = 0; c < 64; c++) { float d = v[c] - mu; q += d * d; }
    float rinv = rsqrtf(q * (1.f / 64.f) + 1e-6f);
    float* dst = g_x + (size_t)bi * CCH * HWPIX + hw;
#pragma unroll
    for (int c = 0; c < 64; c++)
        dst[c * HWPIX] = (v[c] - mu) * rinv * w[c] + b[c];
}

// ---------------- K2: per-(b,c) spatial mean of g_x ------------------------
__global__ void mean_kernel() {
    int bc = blockIdx.x;
    const float* src = g_x + (size_t)bc * HWPIX;
    float s = 0.f;
    for (int i = threadIdx.x; i < HWPIX; i += blockDim.x) s += src[i];
#pragma unroll
    for (int o = 16; o > 0; o >>= 1) s += __shfl_down_sync(0xffffffffu, s, o);
    __shared__ float red[16];
    if ((threadIdx.x & 31) == 0) red[threadIdx.x >> 5] = s;
    __syncthreads();
    if (threadIdx.x == 0) {
        float t = 0.f;
        for (int i = 0; i < (int)(blockDim.x >> 5); i++) t += red[i];
        g_xmean[bc] = t * (1.f / HWPIX);
    }
}

// ---------------- K3: sca = 1x1 conv on pooled means -----------------------
__global__ void sca_kernel(const float* __restrict__ w, const float* __restrict__ b) {
    int t = threadIdx.x;
    if (t < NB * CCH) {
        int bi = t >> 6, c = t & 63;
        float a = b[c];
#pragma unroll
        for (int k = 0; k < 64; k++) a += w[c * 64 + k] * g_xmean[bi * 64 + k];
        g_sca[t] = a;
    }
}

// ---------------- K4: attention path (grouped3x3 + gate + 1x1) -------------
__global__ void att_kernel(const float* __restrict__ c2a_w, const float* __restrict__ c2a_b,
                           const float* __restrict__ c2b_w, const float* __restrict__ c2b_b,
                           const float* __restrict__ attgamma) {
    __shared__ float wa[32 * 18];
    __shared__ float ba[32];
    __shared__ float wbT[16 * 32]; // [j][n]
    __shared__ float bb[32], ag[32];
    for (int i = threadIdx.x; i < 576; i += blockDim.x) wa[i] = c2a_w[i];
    if (threadIdx.x < 32) {
        ba[threadIdx.x] = c2a_b[threadIdx.x];
        bb[threadIdx.x] = c2b_b[threadIdx.x];
        ag[threadIdx.x] = attgamma[threadIdx.x];
    }
    for (int i = threadIdx.x; i < 512; i += blockDim.x) {
        int j = i >> 5, n = i & 31;
        wbT[i] = c2b_w[n * 16 + j];
    }
    __syncthreads();
    int p = blockIdx.x * blockDim.x + threadIdx.x;
    if (p >= NPIX) return;
    int bi = p / HWPIX, hw = p - bi * HWPIX;
    int h = hw / WDx, w = hw - h * WDx;
    const float* xb = g_x + (size_t)bi * CCH * HWPIX;
    float att_acc[32];
#pragma unroll
    for (int n = 0; n < 32; n++) att_acc[n] = 0.f;
#pragma unroll 4
    for (int j = 0; j < 16; j++) {
        float t0 = ba[j], t1 = ba[j + 16];
#pragma unroll
        for (int l = 0; l < 2; l++) {
            const float* xp0 = xb + (2 * j + l) * HWPIX;
            const float* xp1 = xb + (2 * (j + 16) + l) * HWPIX;
#pragma unroll
            for (int dy = 0; dy < 3; dy++) {
                int hy = h + dy - 1;
                bool vy = ((unsigned)hy < HT);
#pragma unroll
                for (int dx = 0; dx < 3; dx++) {
                    int wx = w + dx - 1;
                    bool ok = vy && ((unsigned)wx < WDx);
                    int off = hy * WDx + wx;
                    float x0 = ok ? xp0[off] : 0.f;
                    float x1 = ok ? xp1[off] : 0.f;
                    t0 += wa[j * 18 + l * 9 + dy * 3 + dx] * x0;
                    t1 += wa[(j + 16) * 18 + l * 9 + dy * 3 + dx] * x1;
                }
            }
        }
        float gj = t0 * t1;
        const float4* wp = (const float4*)&wbT[j * 32];
#pragma unroll
        for (int n4 = 0; n4 < 8; n4++) {
            float4 wv = wp[n4];
            att_acc[4 * n4 + 0] += wv.x * gj;
            att_acc[4 * n4 + 1] += wv.y * gj;
            att_acc[4 * n4 + 2] += wv.z * gj;
            att_acc[4 * n4 + 3] += wv.w * gj;
        }
    }
    float* dst = g_att + (size_t)bi * NSETC * HWPIX + hw;
#pragma unroll
    for (int n = 0; n < 32; n++)
        dst[n * HWPIX] = (att_acc[n] + bb[n]) * ag[n];
}

// ---------------- K5: 1x1 conv 64->64 (c11a) on g_x -> g_u1 ----------------
__global__ void conv1x1_u1(const float* __restrict__ w, const float* __restrict__ b) {
    __shared__ float ws[4096];
    __shared__ float bs[64];
    for (int i = threadIdx.x; i < 4096; i += blockDim.x) ws[i] = w[i];
    if (threadIdx.x < 64) bs[threadIdx.x] = b[threadIdx.x];
    __syncthreads();
    int p = blockIdx.x * blockDim.x + threadIdx.x;
    if (p >= NPIX) return;
    int bi = p / HWPIX, hw = p - bi * HWPIX;
    const float* src = g_x + (size_t)bi * CCH * HWPIX + hw;
    float xin[64];
#pragma unroll
    for (int i = 0; i < 64; i++) xin[i] = src[i * HWPIX];
    float* dst = g_u1 + (size_t)bi * CCH * HWPIX + hw;
#pragma unroll 4
    for (int o = 0; o < 64; o++) {
        float a = bs[o];
        const float4* wp = (const float4*)&ws[o * 64];
#pragma unroll
        for (int i4 = 0; i4 < 16; i4++) {
            float4 wv = wp[i4];
            a += wv.x * xin[4 * i4] + wv.y * xin[4 * i4 + 1] +
                 wv.z * xin[4 * i4 + 2] + wv.w * xin[4 * i4 + 3];
        }
        dst[o * HWPIX] = a;
    }
}

// ---------------- K6: grouped 5x5 conv, 4 groups per block -----------------
__global__ void uf_kernel(const float* __restrict__ w5, const float* __restrict__ b5) {
    __shared__ float ws[1600]; // [4 local groups][ic][kk][oc]
    __shared__ float bs[16];
    int g0 = blockIdx.y * 4;
    for (int i = threadIdx.x; i < 1600; i += blockDim.x) {
        int oc = i & 3;
        int r = i >> 2;          // gl*100 + ic*25 + kk
        int gl = r / 100;
        int r2 = r - gl * 100;
        int ic = r2 / 25, kk = r2 - ic * 25;
        ws[i] = w5[(((g0 + gl) * 4 + oc) * 4 + ic) * 25 + kk];
    }
    if (threadIdx.x < 16) bs[threadIdx.x] = b5[g0 * 4 + threadIdx.x];
    __syncthreads();
    int p = blockIdx.x * blockDim.x + threadIdx.x;
    if (p >= NPIX) return;
    int bi = p / HWPIX, hw = p - bi * HWPIX;
    int h = hw / WDx, w = hw - h * WDx;
    const float* ub = g_u1 + (size_t)bi * CCH * HWPIX;
    float* dst = g_uf + (size_t)bi * CCH * HWPIX + hw;
#pragma unroll
    for (int gl = 0; gl < 4; gl++) {
        int g = g0 + gl;
        float a0 = bs[gl * 4 + 0], a1 = bs[gl * 4 + 1], a2 = bs[gl * 4 + 2], a3 = bs[gl * 4 + 3];
        const float* gin = ub + (g * 4) * HWPIX;
#pragma unroll
        for (int dy = 0; dy < 5; dy++) {
            int hy = h + dy - 2;
            bool vy = ((unsigned)hy < HT);
#pragma unroll
            for (int dx = 0; dx < 5; dx++) {
                int wx = w + dx - 2;
                bool ok = vy && ((unsigned)wx < WDx);
                int off = hy * WDx + wx;
                int kk = dy * 5 + dx;
#pragma unroll
                for (int ic = 0; ic < 4; ic++) {
                    float v = ok ? gin[ic * HWPIX + off] : 0.f;
                    const float4 wv = *(const float4*)&ws[(gl * 100 + ic * 25 + kk) * 4];
                    a0 += wv.x * v; a1 += wv.y * v; a2 += wv.z * v; a3 += wv.w * v;
                }
            }
        }
        dst[(g * 4 + 0) * HWPIX] = a0;
        dst[(g * 4 + 1) * HWPIX] = a1;
        dst[(g * 4 + 2) * HWPIX] = a2;
        dst[(g * 4 + 3) * HWPIX] = a3;
    }
}

// ---------------- K7: fused KBA (f32x2, 4 groups/block, conflict-free) -----
#define KBA_SMEM_BYTES (37 * 128 * 8 + 37 * 64 * 8 + 32 * 65 * 8)
__global__ void kba_kernel(const float* __restrict__ ga1) {
    extern __shared__ char smem[];
    ull* Ws2     = (ull*)smem;                                // [37][128] interleaved
    ull* patch2s = (ull*)(smem + 37 * 128 * 8);               // [37][64]
    ull* att2s   = (ull*)(smem + 37 * 128 * 8 + 37 * 64 * 8); // [32][65]

    int tid = threadIdx.x;
    int bi  = blockIdx.x / (HWPIX / 128);
    int hw0 = (blockIdx.x % (HWPIX / 128)) * 128;
    int g0  = blockIdx.y * 4;

    for (int idx = tid; idx < 32 * 64; idx += 256) {
        int n = idx >> 6, pp = idx & 63;
        const float2 v = *(const float2*)&g_att[((size_t)bi * 32 + n) * HWPIX + hw0 + 2 * pp];
        att2s[n * 65 + pp] = pack2(v.x, v.y);
    }

    int m_blk = tid & 15;
    int pp0   = (tid >> 4) * 4;
    int o_out = m_blk >> 2;
    int n0    = (m_blk & 3) * 8;

    for (int gi = 0; gi < 4; gi++) {
        int g = g0 + gi;
        __syncthreads();
        const ull* wsrc = g_kbwT2 + (size_t)g * 37 * 128;
        for (int idx = tid; idx < 37 * 128; idx += 256) Ws2[idx] = wsrc[idx];
        for (int idx = tid; idx < 36 * 64; idx += 256) {
            int k = idx >> 6, pp = idx & 63;
            int ci = k / 9, kk = k - ci * 9;
            int dy = kk / 3, dx = kk - dy * 3;
            const float* ufc = g_uf + ((size_t)bi * 64 + g * 4 + ci) * HWPIX;
            float v0, v1;
            {
                int p = hw0 + 2 * pp;
                int h = p / WDx, w = p - h * WDx;
                int hy = h + dy - 1, wx = w + dx - 1;
                v0 = ((unsigned)hy < HT && (unsigned)wx < WDx) ? ufc[hy * WDx + wx] : 0.f;
            }
            {
                int p = hw0 + 2 * pp + 1;
                int h = p / WDx, w = p - h * WDx;
                int hy = h + dy - 1, wx = w + dx - 1;
                v1 = ((unsigned)hy < HT && (unsigned)wx < WDx) ? ufc[hy * WDx + wx] : 0.f;
            }
            patch2s[idx] = pack2(v0, v1);
        }
        if (tid < 64) patch2s[36 * 64 + tid] = pack2(1.f, 1.f);
        __syncthreads();

        ull acc[8][4];
#pragma unroll
        for (int j = 0; j < 8; j++)
#pragma unroll
            for (int q = 0; q < 4; q++) acc[j][q] = 0ull;

        for (int k = 0; k < 37; k++) {
            const ull* pvp = &patch2s[k * 64 + pp0];
            ull pv0 = pvp[0], pv1 = pvp[1], pv2 = pvp[2], pv3 = pvp[3];
            const ull* wp = &Ws2[k * 128];
#pragma unroll
            for (int j = 0; j < 8; j++) {
                ull wj = wp[j * 16 + m_blk];   // conflict-free: bank pair 2*m_blk
                acc[j][0] = fma2(wj, pv0, acc[j][0]);
                acc[j][1] = fma2(wj, pv1, acc[j][1]);
                acc[j][2] = fma2(wj, pv2, acc[j][2]);
                acc[j][3] = fma2(wj, pv3, acc[j][3]);
            }
        }

        int c = g * 4 + o_out;
#pragma unroll
        for (int q = 0; q < 4; q++) {
            ull part = 0ull;
#pragma unroll
            for (int j = 0; j < 8; j++)
                part = fma2(att2s[(n0 + j) * 65 + pp0 + q], acc[j][q], part);
            part = add2(part, __shfl_xor_sync(0xffffffffu, part, 1));
            part = add2(part, __shfl_xor_sync(0xffffffffu, part, 2));
            if ((tid & 3) == 0) {
                ull ufc2 = patch2s[(o_out * 9 + 4) * 64 + pp0 + q];
                ull ga2  = dup2(ga1[c]);
                ull z2 = fma2(ga2, part, ufc2);   // sca folded into conv3
                float2 zo;
                asm("mov.b64 {%0, %1}, %2;" : "=f"(zo.x), "=f"(zo.y) : "l"(z2));
                *(float2*)&g_z[((size_t)bi * 64 + c) * HWPIX + hw0 + 2 * (pp0 + q)] = zo;
            }
        }
    }
}

// ---------------- K8: conv3 (1x1, input*sca) + beta residual -> g_y --------
__global__ void conv3_res_kernel(const float* __restrict__ inp,
                                 const float* __restrict__ w,
                                 const float* __restrict__ b,
                                 const float* __restrict__ beta) {
    __shared__ float ws[4096];
    __shared__ float bs[64];
    __shared__ float ss[64];
    int bi0 = (blockIdx.x * (int)blockDim.x) / HWPIX;
    for (int i = threadIdx.x; i < 4096; i += blockDim.x) ws[i] = w[i];
    if (threadIdx.x < 64) {
        bs[threadIdx.x] = b[threadIdx.x];
        ss[threadIdx.x] = g_sca[bi0 * 64 + threadIdx.x];
    }
    __syncthreads();
    int p = blockIdx.x * blockDim.x + threadIdx.x;
    if (p >= NPIX) return;
    int bi = p / HWPIX, hw = p - bi * HWPIX;
    const float* src = g_z + (size_t)bi * CCH * HWPIX + hw;
    const float* rsd = inp + (size_t)bi * CCH * HWPIX + hw;
    float xin[64];
#pragma unroll
    for (int i = 0; i < 64; i++) xin[i] = src[i * HWPIX] * ss[i];
    float* dst = g_y + (size_t)bi * CCH * HWPIX + hw;
#pragma unroll 4
    for (int o = 0; o < 64; o++) {
        float a = bs[o];
        const float4* wp = (const float4*)&ws[o * 64];
#pragma unroll
        for (int i4 = 0; i4 < 16; i4++) {
            float4 wv = wp[i4];
            a += wv.x * xin[4 * i4] + wv.y * xin[4 * i4 + 1] +
                 wv.z * xin[4 * i4 + 2] + wv.w * xin[4 * i4 + 3];
        }
        dst[o * HWPIX] = rsd[o * HWPIX] + a * beta[o];
    }
}

// ---------------- K9a: LN2 + conv4 + gate -> g_gate ------------------------
__global__ void ffn_gate_kernel(const float* __restrict__ ln2w, const float* __restrict__ ln2b,
                                const float* __restrict__ w4, const float* __restrict__ b4) {
    __shared__ float ws[8192]; // w4 [j][i]
    for (int i = threadIdx.x; i < 8192; i += blockDim.x) ws[i] = w4[i];
    __syncthreads();
    int p = blockIdx.x * blockDim.x + threadIdx.x;
    if (p >= NPIX) return;
    int bi = p / HWPIX, hw = p - bi * HWPIX;
    const float* yb = g_y + (size_t)bi * CCH * HWPIX + hw;
    float v[64];
    float s = 0.f;
#pragma unroll
    for (int c = 0; c < 64; c++) { v[c] = yb[c * HWPIX]; s += v[c]; }
    float mu = s * (1.f / 64.f);
    float q = 0.f;
#pragma unroll
    for (int c = 0; c < 64; c++) { float d = v[c] - mu; q += d * d; }
    float rinv = rsqrtf(q * (1.f / 64.f) + 1e-6f);
#pragma unroll
    for (int c = 0; c < 64; c++)
        v[c] = (v[c] - mu) * rinv * ln2w[c] + ln2b[c];   // xn overwrites v
    float* dst = g_gate + (size_t)bi * CCH * HWPIX + hw;
#pragma unroll 2
    for (int j = 0; j < 64; j++) {
        float a = b4[j], bb = b4[j + 64];
        const float4* wpa = (const float4*)&ws[j * 64];
        const float4* wpb = (const float4*)&ws[(j + 64) * 64];
#pragma unroll
        for (int i4 = 0; i4 < 16; i4++) {
            float4 wva = wpa[i4];
            float4 wvb = wpb[i4];
            a  += wva.x * v[4 * i4] + wva.y * v[4 * i4 + 1] + wva.z * v[4 * i4 + 2] + wva.w * v[4 * i4 + 3];
            bb += wvb.x * v[4 * i4] + wvb.y * v[4 * i4 + 1] + wvb.z * v[4 * i4 + 2] + wvb.w * v[4 * i4 + 3];
        }
        dst[j * HWPIX] = a * bb;
    }
}

// ---------------- K9b: conv5 + gamma residual -> out ------------------------
__global__ void ffn_out_kernel(const float* __restrict__ w5, const float* __restrict__ b5,
                               const float* __restrict__ gamma, float* __restrict__ out) {
    __shared__ float ws[4096];
    __shared__ float bs[64], gs[64];
    for (int i = threadIdx.x; i < 4096; i += blockDim.x) ws[i] = w5[i];
    if (threadIdx.x < 64) { bs[threadIdx.x] = b5[threadIdx.x]; gs[threadIdx.x] = gamma[threadIdx.x]; }
    __syncthreads();
    int p = blockIdx.x * blockDim.x + threadIdx.x;
    if (p >= NPIX) return;
    int bi = p / HWPIX, hw = p - bi * HWPIX;
    const float* gb = g_gate + (size_t)bi * CCH * HWPIX + hw;
    const float* yb = g_y + (size_t)bi * CCH * HWPIX + hw;
    float xin[64];
#pragma unroll
    for (int i = 0; i < 64; i++) xin[i] = gb[i * HWPIX];
    float* dst = out + (size_t)bi * CCH * HWPIX + hw;
#pragma unroll 4
    for (int o = 0; o < 64; o++) {
        float a = bs[o];
        const float4* wp = (const float4*)&ws[o * 64];
#pragma unroll
        for (int i4 = 0; i4 < 16; i4++) {
            float4 wv = wp[i4];
            a += wv.x * xin[4 * i4] + wv.y * xin[4 * i4 + 1] +
                 wv.z * xin[4 * i4 + 2] + wv.w * xin[4 * i4 + 3];
        }
        dst[o * HWPIX] = yb[o * HWPIX] + a * gs[o];
    }
}

// ---------------------------------------------------------------------------
extern "C" void kernel_launch(void* const* d_in, const int* in_sizes, int n_in,
                              void* d_out, int out_size) {
    const float* inp      = (const float*)d_in[0];
    const float* ln1_w    = (const float*)d_in[1];
    const float* ln1_b    = (const float*)d_in[2];
    const float* ln2_w    = (const float*)d_in[3];
    const float* ln2_b    = (const float*)d_in[4];
    const float* sca_w    = (const float*)d_in[5];
    const float* sca_b    = (const float*)d_in[6];
    const float* c11a_w   = (const float*)d_in[7];
    const float* c11a_b   = (const float*)d_in[8];
    const float* c11b_w   = (const float*)d_in[9];
    const float* c11b_b   = (const float*)d_in[10];
    const float* c2a_w    = (const float*)d_in[11];
    const float* c2a_b    = (const float*)d_in[12];
    const float* c2b_w    = (const float*)d_in[13];
    const float* c2b_b    = (const float*)d_in[14];
    const float* conv3_w  = (const float*)d_in[15];
    const float* conv3_b  = (const float*)d_in[16];
    const float* conv4_w  = (const float*)d_in[17];
    const float* conv4_b  = (const float*)d_in[18];
    const float* conv5_w  = (const float*)d_in[19];
    const float* conv5_b  = (const float*)d_in[20];
    const float* kb_w     = (const float*)d_in[21];
    const float* kb_b     = (const float*)d_in[22];
    const float* ga1      = (const float*)d_in[23];
    const float* attgamma = (const float*)d_in[24];
    const float* beta     = (const float*)d_in[25];
    const float* gamma    = (const float*)d_in[26];
    float* out = (float*)d_out;

    cudaFuncSetAttribute(kba_kernel, cudaFuncAttributeMaxDynamicSharedMemorySize,
                         KBA_SMEM_BYTES);

    kbw_prep_kernel<<<(16 * 37 * 128 + 255) / 256, 256>>>(kb_w, kb_b);
    ln1_kernel<<<NPIX / 256, 256>>>(inp, ln1_w, ln1_b);
    conv1x1_u1<<<NPIX / 256, 256>>>(c11a_w, c11a_b);
    {
        dim3 grid(NPIX / 256, 4);
        uf_kernel<<<grid, 256>>>(c11b_w, c11b_b);
    }
    att_kernel<<<NPIX / 256, 256>>>(c2a_w, c2a_b, c2b_w, c2b_b, attgamma);
    {
        dim3 grid(NPIX / 128, 4);
        kba_kernel<<<grid, 256, KBA_SMEM_BYTES>>>(ga1);
    }
    mean_kernel<<<NB * CCH, 512>>>();
    sca_kernel<<<1, 128>>>(sca_w, sca_b);
    conv3_res_kernel<<<NPIX / 256, 256>>>(inp, conv3_w, conv3_b, beta);
    ffn_gate_kernel<<<NPIX / 256, 256>>>(ln2_w, ln2_b, conv4_w, conv4_b);
    ffn_out_kernel<<<NPIX / 256, 256>>>(conv5_w, conv5_b, gamma, out);
}